// round 1
// baseline (speedup 1.0000x reference)
#include <cuda_runtime.h>
#include <cuda_bf16.h>
#include <math_constants.h>

#define B_  8
#define SQ_ 128
#define SK_ 1024
#define U_  256

// Scratch for projected q and k (allocation-free rule: __device__ globals)
__device__ float g_q[B_ * SQ_ * U_];   // 1 MB
__device__ float g_k[B_ * SK_ * U_];   // 8 MB

__device__ __forceinline__ float tanha(float x) {
    float y;
    asm("tanh.approx.f32 %0, %1;" : "=f"(y) : "f"(x));
    return y;
}

// ---------------------------------------------------------------------------
// Generic 64x64 register-tiled SGEMM: C = A @ B  (row-major), batched via z.
// BK=16, 256 threads, 4x4 micro-tile per thread. M%64==0, N%64==0, K%16==0.
// ---------------------------------------------------------------------------
__global__ void gemm_tiled(const float* __restrict__ A, const float* __restrict__ Bm,
                           float* __restrict__ C, int M, int N, int K,
                           long long sA, long long sB, long long sC) {
    A  += (long long)blockIdx.z * sA;
    Bm += (long long)blockIdx.z * sB;
    C  += (long long)blockIdx.z * sC;

    __shared__ float As[16][68];   // [k][m], padded: 68 floats = 17*16B (float4 aligned)
    __shared__ float Bs[16][64];   // [k][n]

    const int tid = threadIdx.x;
    const int tx = tid & 15;       // n dir
    const int ty = tid >> 4;       // m dir
    const int m0 = blockIdx.y * 64;
    const int n0 = blockIdx.x * 64;

    const int arow = tid >> 2;          // 0..63
    const int acol = (tid & 3) << 2;    // 0,4,8,12
    const int brow = tid >> 4;          // 0..15
    const int bcol = (tid & 15) << 2;   // 0..60

    float acc[4][4];
#pragma unroll
    for (int r = 0; r < 4; r++)
#pragma unroll
        for (int c = 0; c < 4; c++) acc[r][c] = 0.0f;

    for (int k0 = 0; k0 < K; k0 += 16) {
        float4 av = *(const float4*)&A[(long long)(m0 + arow) * K + k0 + acol];
        float4 bv = *(const float4*)&Bm[(long long)(k0 + brow) * N + n0 + bcol];
        As[acol + 0][arow] = av.x;
        As[acol + 1][arow] = av.y;
        As[acol + 2][arow] = av.z;
        As[acol + 3][arow] = av.w;
        *(float4*)&Bs[brow][bcol] = bv;
        __syncthreads();
#pragma unroll
        for (int k = 0; k < 16; k++) {
            float4 a4 = *(const float4*)&As[k][ty << 2];
            float4 b4 = *(const float4*)&Bs[k][tx << 2];
            float ar[4] = {a4.x, a4.y, a4.z, a4.w};
            float br[4] = {b4.x, b4.y, b4.z, b4.w};
#pragma unroll
            for (int r = 0; r < 4; r++)
#pragma unroll
                for (int c = 0; c < 4; c++) acc[r][c] += ar[r] * br[c];
        }
        __syncthreads();
    }

#pragma unroll
    for (int r = 0; r < 4; r++) {
        float4 o = make_float4(acc[r][0], acc[r][1], acc[r][2], acc[r][3]);
        *(float4*)&C[(long long)(m0 + (ty << 2) + r) * N + n0 + (tx << 2)] = o;
    }
}

// ---------------------------------------------------------------------------
// Scores: score[b,i,j] = sum_u tanh(q[b,i,u] + k[b,j,u]) * wv[u]
// CTA: (j-block 64, i-block 16, batch). 256 threads; thread = (tx=j lane, ty=i),
// covers 1 i x 4 j (j = tx + 16r). u chunked by 64 through SMEM.
// ---------------------------------------------------------------------------
#define TQ 16
#define TJ 64
#define UC 64

__global__ void scores_kernel(const float* __restrict__ wv, float* __restrict__ attn) {
    const int b  = blockIdx.z;
    const int ib = blockIdx.y;
    const int jb = blockIdx.x;

    __shared__ float qs[TQ][U_];        // 16 KB
    __shared__ float ks[TJ][UC + 4];    // padded rows: 68 floats = float4-aligned
    __shared__ float wvs[U_];

    const int tid = threadIdx.x;
    const int tx = tid & 15;
    const int ty = tid >> 4;

    // load q tile [16][256] (1024 float4 / 256 threads = 4 each)
    const float* qbase = g_q + ((long long)b * SQ_ + ib * TQ) * U_;
#pragma unroll
    for (int l = 0; l < 4; l++) {
        int idx = tid + l * 256;
        int row = idx >> 6;            // 64 float4 per row
        int col = (idx & 63) << 2;
        *(float4*)&qs[row][col] = *(const float4*)&qbase[(long long)row * U_ + col];
    }
    if (tid < 64) *(float4*)&wvs[tid << 2] = *(const float4*)&wv[tid << 2];

    float acc[4] = {0.f, 0.f, 0.f, 0.f};
    const float* kbase = g_k + ((long long)b * SK_ + jb * TJ) * U_;

    for (int uc = 0; uc < U_; uc += UC) {
        __syncthreads();
        // load k chunk [64][64] (1024 float4 / 256 threads = 4 each)
#pragma unroll
        for (int l = 0; l < 4; l++) {
            int idx = tid + l * 256;
            int row = idx >> 4;        // 16 float4 per row
            int col = (idx & 15) << 2;
            *(float4*)&ks[row][col] = *(const float4*)&kbase[(long long)row * U_ + uc + col];
        }
        __syncthreads();

#pragma unroll
        for (int uu = 0; uu < UC; uu += 4) {
            float4 qv = *(const float4*)&qs[ty][uc + uu];
            float4 wq = *(const float4*)&wvs[uc + uu];
#pragma unroll
            for (int r = 0; r < 4; r++) {
                float4 kv = *(const float4*)&ks[tx + 16 * r][uu];
                acc[r] += tanha(qv.x + kv.x) * wq.x;
                acc[r] += tanha(qv.y + kv.y) * wq.y;
                acc[r] += tanha(qv.z + kv.z) * wq.z;
                acc[r] += tanha(qv.w + kv.w) * wq.w;
            }
        }
    }

    long long base = ((long long)b * SQ_ + ib * TQ + ty) * SK_ + jb * TJ;
#pragma unroll
    for (int r = 0; r < 4; r++) attn[base + tx + 16 * r] = acc[r];
}

// ---------------------------------------------------------------------------
// Row softmax over SK=1024, in place. One CTA (256 threads) per (b,i) row.
// ---------------------------------------------------------------------------
__global__ void softmax_kernel(float* __restrict__ attn) {
    float* p = attn + (long long)blockIdx.x * SK_;
    const int tid = threadIdx.x;
    __shared__ float red[8];

    float4 x = *(const float4*)&p[tid << 2];
    float m = fmaxf(fmaxf(x.x, x.y), fmaxf(x.z, x.w));
#pragma unroll
    for (int o = 16; o; o >>= 1) m = fmaxf(m, __shfl_xor_sync(0xffffffffu, m, o));
    if ((tid & 31) == 0) red[tid >> 5] = m;
    __syncthreads();
    float M = red[0];
#pragma unroll
    for (int w = 1; w < 8; w++) M = fmaxf(M, red[w]);

    float4 e;
    e.x = __expf(x.x - M);
    e.y = __expf(x.y - M);
    e.z = __expf(x.z - M);
    e.w = __expf(x.w - M);
    float s = (e.x + e.y) + (e.z + e.w);
#pragma unroll
    for (int o = 16; o; o >>= 1) s += __shfl_xor_sync(0xffffffffu, s, o);
    __syncthreads();                 // everyone done reading red[] (max phase)
    if ((tid & 31) == 0) red[tid >> 5] = s;
    __syncthreads();
    float S = 0.f;
#pragma unroll
    for (int w = 0; w < 8; w++) S += red[w];
    float inv = 1.0f / S;
    e.x *= inv; e.y *= inv; e.z *= inv; e.w *= inv;
    *(float4*)&p[tid << 2] = e;
}

// ---------------------------------------------------------------------------
extern "C" void kernel_launch(void* const* d_in, const int* in_sizes, int n_in,
                              void* d_out, int out_size) {
    const float* query = (const float*)d_in[0];
    const float* key   = (const float*)d_in[1];
    const float* value = (const float*)d_in[2];
    const float* Wq    = (const float*)d_in[3];
    const float* Wk    = (const float*)d_in[4];
    const float* wv    = (const float*)d_in[5];

    float* out  = (float*)d_out;
    float* ctx  = out;                           // [B, SQ, U]
    float* attn = out + (long long)B_ * SQ_ * U_; // [B, SQ, SK]

    void* pq = nullptr; void* pk = nullptr;
    cudaGetSymbolAddress(&pq, g_q);
    cudaGetSymbolAddress(&pk, g_k);
    float* dq = (float*)pq;
    float* dk = (float*)pk;

    // 1) Projections: q = query @ Wq  (M=1024), k = key @ Wk (M=8192)
    gemm_tiled<<<dim3(U_ / 64, (B_ * SQ_) / 64, 1), 256>>>(
        query, Wq, dq, B_ * SQ_, U_, U_, 0, 0, 0);
    gemm_tiled<<<dim3(U_ / 64, (B_ * SK_) / 64, 1), 256>>>(
        key, Wk, dk, B_ * SK_, U_, U_, 0, 0, 0);

    // 2) Raw scores into the attention-weights output region
    scores_kernel<<<dim3(SK_ / TJ, SQ_ / TQ, B_), 256>>>(wv, attn);

    // 3) Softmax in place (one row per CTA)
    softmax_kernel<<<B_ * SQ_, 256>>>(attn);

    // 4) context = attn @ value (batched GEMM, M=128, N=256, K=1024)
    gemm_tiled<<<dim3(U_ / 64, SQ_ / 64, B_), 256>>>(
        attn, value, ctx, SQ_, U_, SK_,
        (long long)SQ_ * SK_, (long long)SK_ * U_, (long long)SQ_ * U_);
}

// round 4
// speedup vs baseline: 1.0042x; 1.0042x over previous
#include <cuda_runtime.h>
#include <cuda_bf16.h>
#include <math_constants.h>

#define B_  8
#define SQ_ 128
#define SK_ 1024
#define U_  256

// Scratch for projected q and k (allocation-free rule: __device__ globals)
__device__ float g_q[B_ * SQ_ * U_];   // 1 MB
__device__ float g_k[B_ * SK_ * U_];   // 8 MB

__device__ __forceinline__ float tanha(float x) {
    float y;
    asm("tanh.approx.f32 %0, %1;" : "=f"(y) : "f"(x));
    return y;
}

// ---------------------------------------------------------------------------
// 64x64 register-tiled SGEMM (k-projection): C = A @ B, 256 thr, 4x4 micro.
// ---------------------------------------------------------------------------
__global__ void gemm_tiled(const float* __restrict__ A, const float* __restrict__ Bm,
                           float* __restrict__ C, int M, int N, int K) {
    __shared__ float As[16][68];
    __shared__ float Bs[16][64];

    const int tid = threadIdx.x;
    const int tx = tid & 15;
    const int ty = tid >> 4;
    const int m0 = blockIdx.y * 64;
    const int n0 = blockIdx.x * 64;

    const int arow = tid >> 2;
    const int acol = (tid & 3) << 2;
    const int brow = tid >> 4;
    const int bcol = (tid & 15) << 2;

    float acc[4][4];
#pragma unroll
    for (int r = 0; r < 4; r++)
#pragma unroll
        for (int c = 0; c < 4; c++) acc[r][c] = 0.0f;

    for (int k0 = 0; k0 < K; k0 += 16) {
        float4 av = *(const float4*)&A[(long long)(m0 + arow) * K + k0 + acol];
        float4 bv = *(const float4*)&Bm[(long long)(k0 + brow) * N + n0 + bcol];
        As[acol + 0][arow] = av.x;
        As[acol + 1][arow] = av.y;
        As[acol + 2][arow] = av.z;
        As[acol + 3][arow] = av.w;
        *(float4*)&Bs[brow][bcol] = bv;
        __syncthreads();
#pragma unroll
        for (int k = 0; k < 16; k++) {
            float4 a4 = *(const float4*)&As[k][ty << 2];
            float4 b4 = *(const float4*)&Bs[k][tx << 2];
            float ar[4] = {a4.x, a4.y, a4.z, a4.w};
            float br[4] = {b4.x, b4.y, b4.z, b4.w};
#pragma unroll
            for (int r = 0; r < 4; r++)
#pragma unroll
                for (int c = 0; c < 4; c++) acc[r][c] += ar[r] * br[c];
        }
        __syncthreads();
    }

#pragma unroll
    for (int r = 0; r < 4; r++) {
        float4 o = make_float4(acc[r][0], acc[r][1], acc[r][2], acc[r][3]);
        *(float4*)&C[(long long)(m0 + (ty << 2) + r) * N + n0 + (tx << 2)] = o;
    }
}

// ---------------------------------------------------------------------------
// 32x64-tile SGEMM (q-projection + context): more CTAs for small-M problems.
// 256 threads, 2x4 micro-tile, BK=16. Batched via blockIdx.z strides.
// ---------------------------------------------------------------------------
__global__ void gemm_32x64(const float* __restrict__ A, const float* __restrict__ Bm,
                           float* __restrict__ C, int M, int N, int K,
                           long long sA, long long sB, long long sC) {
    A  += (long long)blockIdx.z * sA;
    Bm += (long long)blockIdx.z * sB;
    C  += (long long)blockIdx.z * sC;

    __shared__ float As[16][34];   // [k][m], padded
    __shared__ float Bs[16][64];   // [k][n]

    const int tid = threadIdx.x;
    const int tx = tid & 15;       // n
    const int ty = tid >> 4;       // m (16 -> 2 rows each)
    const int m0 = blockIdx.y * 32;
    const int n0 = blockIdx.x * 64;

    const int arow = tid >> 3;          // 0..31
    const int acol = (tid & 7) << 1;    // 0,2,..,14
    const int brow = tid >> 4;          // 0..15
    const int bcol = (tid & 15) << 2;   // 0..60

    float acc0[4] = {0.f, 0.f, 0.f, 0.f};
    float acc1[4] = {0.f, 0.f, 0.f, 0.f};

    for (int k0 = 0; k0 < K; k0 += 16) {
        float2 av = *(const float2*)&A[(long long)(m0 + arow) * K + k0 + acol];
        float4 bv = *(const float4*)&Bm[(long long)(k0 + brow) * N + n0 + bcol];
        As[acol + 0][arow] = av.x;
        As[acol + 1][arow] = av.y;
        *(float4*)&Bs[brow][bcol] = bv;
        __syncthreads();
#pragma unroll
        for (int k = 0; k < 16; k++) {
            float a0 = As[k][(ty << 1) + 0];
            float a1 = As[k][(ty << 1) + 1];
            float4 b4 = *(const float4*)&Bs[k][tx << 2];
            acc0[0] += a0 * b4.x; acc0[1] += a0 * b4.y;
            acc0[2] += a0 * b4.z; acc0[3] += a0 * b4.w;
            acc1[0] += a1 * b4.x; acc1[1] += a1 * b4.y;
            acc1[2] += a1 * b4.z; acc1[3] += a1 * b4.w;
        }
        __syncthreads();
    }

    *(float4*)&C[(long long)(m0 + (ty << 1) + 0) * N + n0 + (tx << 2)] =
        make_float4(acc0[0], acc0[1], acc0[2], acc0[3]);
    *(float4*)&C[(long long)(m0 + (ty << 1) + 1) * N + n0 + (tx << 2)] =
        make_float4(acc1[0], acc1[1], acc1[2], acc1[3]);
}

// ---------------------------------------------------------------------------
// Scores v2: thread owns one j-column; k[j, u-chunk] lives in registers
// (double-buffered LDG), q read via broadcast LDS. Pure MUFU-bound.
// score[b,i,j] = sum_u tanh(q[b,i,u] + k[b,j,u]) * wv[u]
// CTA: 256 threads = 256 j, i-tile = 16. Grid (SK/256, SQ/16, B).
// ---------------------------------------------------------------------------
#define TQ 16

__global__ void scores_kernel(const float* __restrict__ wv, float* __restrict__ attn) {
    const int b  = blockIdx.z;
    const int ib = blockIdx.y;
    const int tid = threadIdx.x;
    const int j  = blockIdx.x * 256 + tid;

    __shared__ float qs[TQ][U_];   // 16 KB
    __shared__ float wvs[U_];

    // load q tile [16][256] (1024 float4 / 256 threads = 4 each), coalesced
    const float* qbase = g_q + ((long long)(b * SQ_ + ib * TQ)) * U_;
#pragma unroll
    for (int l = 0; l < 4; l++) {
        int idx = tid + l * 256;
        int row = idx >> 6;
        int col = (idx & 63) << 2;
        *(float4*)&qs[row][col] = *(const float4*)&qbase[(long long)row * U_ + col];
    }
    if (tid < 64) *(float4*)&wvs[tid << 2] = *(const float4*)&wv[tid << 2];
    __syncthreads();

    const float* kp = g_k + ((long long)(b * SK_) + j) * U_;

    float acc[TQ];
#pragma unroll
    for (int i = 0; i < TQ; i++) acc[i] = 0.0f;

    float4 ka = *(const float4*)&kp[0];
    float4 kb = *(const float4*)&kp[4];

#pragma unroll 4
    for (int uc = 0; uc < U_; uc += 8) {
        // prefetch next chunk; clamp address on the tail (value unused there)
        int un = (uc + 8 < U_) ? uc + 8 : uc;
        float4 kna = *(const float4*)&kp[un];
        float4 knb = *(const float4*)&kp[un + 4];
        float4 w0 = *(const float4*)&wvs[uc];
        float4 w1 = *(const float4*)&wvs[uc + 4];
#pragma unroll
        for (int i = 0; i < TQ; i++) {
            float4 q0 = *(const float4*)&qs[i][uc];        // broadcast
            float4 q1 = *(const float4*)&qs[i][uc + 4];    // broadcast
            float s;
            s  = tanha(q0.x + ka.x) * w0.x;
            s += tanha(q0.y + ka.y) * w0.y;
            s += tanha(q0.z + ka.z) * w0.z;
            s += tanha(q0.w + ka.w) * w0.w;
            s += tanha(q1.x + kb.x) * w1.x;
            s += tanha(q1.y + kb.y) * w1.y;
            s += tanha(q1.z + kb.z) * w1.z;
            s += tanha(q1.w + kb.w) * w1.w;
            acc[i] += s;
        }
        ka = kna;
        kb = knb;
    }

    long long base = ((long long)(b * SQ_ + ib * TQ)) * SK_ + j;
#pragma unroll
    for (int i = 0; i < TQ; i++) attn[base + (long long)i * SK_] = acc[i];
}

// ---------------------------------------------------------------------------
// Row softmax over SK=1024, in place. One CTA (256 threads) per (b,i) row.
// ---------------------------------------------------------------------------
__global__ void softmax_kernel(float* __restrict__ attn) {
    float* p = attn + (long long)blockIdx.x * SK_;
    const int tid = threadIdx.x;
    __shared__ float red[8];

    float4 x = *(const float4*)&p[tid << 2];
    float m = fmaxf(fmaxf(x.x, x.y), fmaxf(x.z, x.w));
#pragma unroll
    for (int o = 16; o; o >>= 1) m = fmaxf(m, __shfl_xor_sync(0xffffffffu, m, o));
    if ((tid & 31) == 0) red[tid >> 5] = m;
    __syncthreads();
    float M = red[0];
#pragma unroll
    for (int w = 1; w < 8; w++) M = fmaxf(M, red[w]);

    float4 e;
    e.x = __expf(x.x - M);
    e.y = __expf(x.y - M);
    e.z = __expf(x.z - M);
    e.w = __expf(x.w - M);
    float s = (e.x + e.y) + (e.z + e.w);
#pragma unroll
    for (int o = 16; o; o >>= 1) s += __shfl_xor_sync(0xffffffffu, s, o);
    __syncthreads();
    if ((tid & 31) == 0) red[tid >> 5] = s;
    __syncthreads();
    float S = 0.f;
#pragma unroll
    for (int w = 0; w < 8; w++) S += red[w];
    float inv = 1.0f / S;
    e.x *= inv; e.y *= inv; e.z *= inv; e.w *= inv;
    *(float4*)&p[tid << 2] = e;
}

// ---------------------------------------------------------------------------
extern "C" void kernel_launch(void* const* d_in, const int* in_sizes, int n_in,
                              void* d_out, int out_size) {
    const float* query = (const float*)d_in[0];
    const float* key   = (const float*)d_in[1];
    const float* value = (const float*)d_in[2];
    const float* Wq    = (const float*)d_in[3];
    const float* Wk    = (const float*)d_in[4];
    const float* wv    = (const float*)d_in[5];

    float* out  = (float*)d_out;
    float* ctx  = out;                            // [B, SQ, U]
    float* attn = out + (long long)B_ * SQ_ * U_; // [B, SQ, SK]

    void* pq = nullptr; void* pk = nullptr;
    cudaGetSymbolAddress(&pq, g_q);
    cudaGetSymbolAddress(&pk, g_k);
    float* dq = (float*)pq;
    float* dk = (float*)pk;

    // 1) Projections
    //    q = query @ Wq  (M=1024): 32x64 tiles -> 128 CTAs
    gemm_32x64<<<dim3(U_ / 64, (B_ * SQ_) / 32, 1), 256>>>(
        query, Wq, dq, B_ * SQ_, U_, U_, 0, 0, 0);
    //    k = key @ Wk    (M=8192): 64x64 tiles -> 512 CTAs
    gemm_tiled<<<dim3(U_ / 64, (B_ * SK_) / 64, 1), 256>>>(
        key, Wk, dk, B_ * SK_, U_, U_);

    // 2) Raw scores into the attention-weights output region
    scores_kernel<<<dim3(SK_ / 256, SQ_ / TQ, B_), 256>>>(wv, attn);

    // 3) Softmax in place
    softmax_kernel<<<B_ * SQ_, 256>>>(attn);

    // 4) context = attn @ value (batched, M=128 N=256 K=1024): 128 CTAs
    gemm_32x64<<<dim3(U_ / 64, SQ_ / 32, B_), 256>>>(
        attn, value, ctx, SQ_, U_, SK_,
        (long long)SQ_ * SK_, (long long)SK_ * U_, (long long)SQ_ * U_);
}